// round 4
// baseline (speedup 1.0000x reference)
#include <cuda_runtime.h>
#include <math.h>
#include <cstdint>

#define BATCH 2048
#define SEQ   200
#define HDIM  512
#define MTOT  (BATCH * SEQ)   // 409600
#define NPLANES 4             // 4 o-tiles of 128 cols

// ---------------- static device scratch (no allocation) ----------------
__device__ float g_l[BATCH * HDIM];          // Wr(last_memory)  [B,512]
__device__ float g_spart[NPLANES][MTOT];     // partial scores
__device__ char  g_Bh[HDIM * HDIM];          // Ur_w quantized hi byte
__device__ char  g_Bl[HDIM * HDIM];          // Ur_w quantized lo byte

// quantization scales: A = 2^-12 * (ah*256 + al),  B = 2^-16 * (bh*256 + bl)
#define QSA 4096.0f
#define QSB 65536.0f
#define K1  2.44140625e-4f      // 2^-28 * 2^16
#define K2  9.5367431640625e-7f // 2^-28 * 2^8

// ======================= helpers =======================
__device__ __forceinline__ uint32_t smem_u32(const void* p) {
    uint32_t a;
    asm("{ .reg .u64 t; cvta.to.shared.u64 t, %1; cvt.u32.u64 %0, t; }"
        : "=r"(a) : "l"(p));
    return a;
}
#define SWZ(off) ((off) ^ (((off) >> 3) & 0x70))

#define LDSM_X4(r, a) \
    asm volatile("ldmatrix.sync.aligned.m8n8.x4.shared.b16 {%0,%1,%2,%3}, [%4];" \
        : "=r"((r)[0]), "=r"((r)[1]), "=r"((r)[2]), "=r"((r)[3]) : "r"(a))
#define LDSM_X2(r, a) \
    asm volatile("ldmatrix.sync.aligned.m8n8.x2.shared.b16 {%0,%1}, [%2];" \
        : "=r"((r)[0]), "=r"((r)[1]) : "r"(a))
#define MMA_S8(d, a, b) \
    asm volatile("mma.sync.aligned.m16n8k32.row.col.s32.s8.s8.s32 " \
        "{%0,%1,%2,%3},{%4,%5,%6,%7},{%8,%9},{%0,%1,%2,%3};" \
        : "+r"((d)[0]), "+r"((d)[1]), "+r"((d)[2]), "+r"((d)[3]) \
        : "r"((a)[0]), "r"((a)[1]), "r"((a)[2]), "r"((a)[3]), \
          "r"((b)[0]), "r"((b)[1]))
#define CPASYNC16(dst, src) \
    asm volatile("cp.async.cg.shared.global [%0], [%1], 16;" \
        :: "r"(dst), "l"(src) : "memory")
#define CPASYNC_COMMIT() asm volatile("cp.async.commit_group;" ::: "memory")
#define CPASYNC_WAITG(n) asm volatile("cp.async.wait_group %0;" :: "n"(n) : "memory")
#define STS128(addr, a, b, c, d) \
    asm volatile("st.shared.v4.b32 [%0], {%1, %2, %3, %4};" \
        :: "r"(addr), "r"(a), "r"(b), "r"(c), "r"(d) : "memory")

__device__ __forceinline__ float fast_tanh(float x) {
    float e = __expf(2.0f * x);
    return 1.0f - __fdividef(2.0f, e + 1.0f);
}
__device__ __forceinline__ void q16(float x, float s, int& hi, int& lo) {
    int v = __float2int_rn(x * s);
    v = v < -32768 ? -32768 : (v > 32639 ? 32639 : v);
    hi = (v + 128) >> 8;          // arithmetic shift -> [-128,127]
    lo = v - (hi << 8);           // [-128,127]
}
__device__ __forceinline__ uint32_t pack4(int a0, int a1, int a2, int a3) {
    return (uint32_t)(a0 & 0xFF) | ((uint32_t)(a1 & 0xFF) << 8) |
           ((uint32_t)(a2 & 0xFF) << 16) | ((uint32_t)(a3 & 0xFF) << 24);
}

// =============================================================================
// B quant kernel: Ur_w fp32 -> (hi, lo) s8 fixed-point
// =============================================================================
__global__ void __launch_bounds__(256)
bquant_kernel(const float* __restrict__ W)
{
    int i = blockIdx.x * 256 + threadIdx.x;      // float4 units, 65536 total
    float4 v = reinterpret_cast<const float4*>(W)[i];
    int h0, l0, h1, l1, h2, l2, h3, l3;
    q16(v.x, QSB, h0, l0); q16(v.y, QSB, h1, l1);
    q16(v.z, QSB, h2, l2); q16(v.w, QSB, h3, l3);
    reinterpret_cast<uint32_t*>(g_Bh)[i] = pack4(h0, h1, h2, h3);
    reinterpret_cast<uint32_t*>(g_Bl)[i] = pack4(l0, l1, l2, l3);
}

// =============================================================================
// K1: l = last_memory @ Wr^T  (SIMT fp32, small; ~52us)
// =============================================================================
__global__ void __launch_bounds__(256)
gemm_l_kernel(const float* __restrict__ A, const float* __restrict__ W)
{
    const int tid = threadIdx.x;
    const int tx  = tid & 15;
    const int ty  = tid >> 4;
    const int m0  = blockIdx.x * 64;
    const int o0  = blockIdx.y * 128;

    __shared__ float As[64][33];
    __shared__ float Ws[128][33];

    float acc[4][8];
#pragma unroll
    for (int i = 0; i < 4; i++)
#pragma unroll
        for (int j = 0; j < 8; j++) acc[i][j] = 0.0f;

    for (int k0 = 0; k0 < HDIM; k0 += 32) {
#pragma unroll
        for (int t = 0; t < 2; t++) {
            int f = t * 256 + tid, r = f >> 3, c4 = (f & 7) << 2;
            float4 v = *reinterpret_cast<const float4*>(&A[(size_t)(m0 + r) * HDIM + k0 + c4]);
            As[r][c4] = v.x; As[r][c4 + 1] = v.y; As[r][c4 + 2] = v.z; As[r][c4 + 3] = v.w;
        }
#pragma unroll
        for (int t = 0; t < 4; t++) {
            int f = t * 256 + tid, r = f >> 3, c4 = (f & 7) << 2;
            float4 v = *reinterpret_cast<const float4*>(&W[(size_t)(o0 + r) * HDIM + k0 + c4]);
            Ws[r][c4] = v.x; Ws[r][c4 + 1] = v.y; Ws[r][c4 + 2] = v.z; Ws[r][c4 + 3] = v.w;
        }
        __syncthreads();
#pragma unroll
        for (int kk = 0; kk < 32; kk++) {
            float a[4], w[8];
#pragma unroll
            for (int i = 0; i < 4; i++) a[i] = As[ty * 4 + i][kk];
#pragma unroll
            for (int j = 0; j < 8; j++) w[j] = Ws[tx + 16 * j][kk];
#pragma unroll
            for (int i = 0; i < 4; i++)
#pragma unroll
                for (int j = 0; j < 8; j++) acc[i][j] += a[i] * w[j];
        }
        __syncthreads();
    }
#pragma unroll
    for (int i = 0; i < 4; i++) {
        int m = m0 + ty * 4 + i;
#pragma unroll
        for (int j = 0; j < 8; j++)
            g_l[(size_t)m * HDIM + o0 + tx + 16 * j] = acc[i][j];
    }
}

// =============================================================================
// K2: int8 3-pass GEMM (m16n8k32.s8) + fused tanh/vre epilogue.
// CTA: 128(m) x ALL 512(n). A quantized once into smem (hi/lo, 4 k-chunks of
// 128); B (s8 hi/lo) double-buffered via cp.async per (ot, chunk).
// Warps 2(m) x 4(n): per warp 64m x 32n, acc hh/mid s32[4][4][4].
// =============================================================================
#define OFF_A    0
#define A_CH     16384          // one 128x128B chunk tile
#define OFF_AL   65536          // lo plane
#define OFF_B    131072
#define B_STG    32768          // bh(16K) + bl(16K)
#define OFF_BL   16384
#define OFF_VRE  196608         // 512 floats
#define OFF_PART 198656         // 128*4 floats
#define SMEM_TOTAL 200704

__device__ __forceinline__ void issue_b(uint32_t dst_base, int o0, int c,
                                        int br, int bhalf)
{
    const char* srcH = g_Bh + (size_t)(o0 + br) * HDIM + c * 128 + bhalf;
    const char* srcL = g_Bl + (size_t)(o0 + br) * HDIM + c * 128 + bhalf;
#pragma unroll
    for (int q = 0; q < 4; q++) {
        uint32_t o = SWZ((uint32_t)(br * 128 + bhalf + q * 16));
        CPASYNC16(dst_base + o,           srcH + q * 16);
        CPASYNC16(dst_base + OFF_BL + o,  srcL + q * 16);
    }
}

__global__ void __launch_bounds__(256, 1)
score_kernel(const float* __restrict__ A,       // all_memory [M,512]
             const float* __restrict__ vre)     // [512]
{
    extern __shared__ char smem[];
    const uint32_t sb  = smem_u32(smem);
    const int tid = threadIdx.x;
    const int wid = tid >> 5;
    const int lid = tid & 31;
    const int wm  = wid >> 2;
    const int wn  = wid & 3;
    const int m0  = blockIdx.x * 128;

    float* svre = reinterpret_cast<float*>(smem + OFF_VRE);
    svre[tid] = vre[tid];
    svre[tid + 256] = vre[tid + 256];

    const int br = tid >> 1, bhalf = (tid & 1) * 64;
    const int ar = tid >> 1, ahalf = (tid & 1) * 64;

    // prologue: B chunk 0 (ot=0,c=0) first for latency
    issue_b(sb + OFF_B, 0, 0, br, bhalf);
    CPASYNC_COMMIT();

    // quantize A once into smem (hi/lo, 4 chunk tiles)
    const float* Arow = A + (size_t)(m0 + ar) * HDIM;
#pragma unroll
    for (int c = 0; c < 4; c++) {
#pragma unroll
        for (int g = 0; g < 4; g++) {
            uint32_t hp[4], lp[4];
#pragma unroll
            for (int q = 0; q < 4; q++) {
                float4 v = *reinterpret_cast<const float4*>(
                    Arow + c * 128 + ahalf + g * 16 + q * 4);
                int h0, l0, h1, l1, h2, l2, h3, l3;
                q16(v.x, QSA, h0, l0); q16(v.y, QSA, h1, l1);
                q16(v.z, QSA, h2, l2); q16(v.w, QSA, h3, l3);
                hp[q] = pack4(h0, h1, h2, h3);
                lp[q] = pack4(l0, l1, l2, l3);
            }
            uint32_t o = SWZ((uint32_t)(ar * 128 + ahalf + g * 16));
            STS128(sb + OFF_A + c * A_CH + o,          hp[0], hp[1], hp[2], hp[3]);
            STS128(sb + OFF_A + OFF_AL + c * A_CH + o, lp[0], lp[1], lp[2], lp[3]);
        }
    }

    int hh[4][4][4], mid[4][4][4];
#pragma unroll
    for (int i = 0; i < 4; i++)
#pragma unroll
        for (int j = 0; j < 4; j++)
#pragma unroll
            for (int q = 0; q < 4; q++) { hh[i][j][q] = 0; mid[i][j][q] = 0; }

#pragma unroll 1
    for (int t = 0; t < 16; t++) {
        const int ot = t >> 2, c = t & 3;
        const uint32_t st = sb + OFF_B + (t & 1) * B_STG;

        if (t < 15) {
            const int tn = t + 1;
            issue_b(sb + OFF_B + ((t + 1) & 1) * B_STG, (tn >> 2) * 128, tn & 3,
                    br, bhalf);
            CPASYNC_COMMIT();
            CPASYNC_WAITG(1);
        } else {
            CPASYNC_WAITG(0);
        }
        __syncthreads();

        // ---- MMAs on A chunk c x B stage ----
#pragma unroll
        for (int ks = 0; ks < 4; ks++) {
            uint32_t ah[4][4], al[4][4], bh4[4][2], bl4[4][2];
#pragma unroll
            for (int mf = 0; mf < 4; mf++) {
                uint32_t row = wm * 64 + mf * 16 + (lid & 15);
                uint32_t kb  = ks * 32 + (lid >> 4) * 16;
                uint32_t o   = SWZ(row * 128 + kb);
                LDSM_X4(ah[mf], sb + OFF_A + c * A_CH + o);
                LDSM_X4(al[mf], sb + OFF_A + OFF_AL + c * A_CH + o);
            }
#pragma unroll
            for (int nf = 0; nf < 4; nf++) {
                uint32_t row = wn * 32 + nf * 8 + (lid & 7);
                uint32_t kb  = ks * 32 + ((lid >> 3) & 1) * 16;
                uint32_t o   = SWZ(row * 128 + kb);
                LDSM_X2(bh4[nf], st + o);
                LDSM_X2(bl4[nf], st + OFF_BL + o);
            }
#pragma unroll
            for (int mf = 0; mf < 4; mf++)
#pragma unroll
                for (int nf = 0; nf < 4; nf++) MMA_S8(hh[mf][nf], ah[mf], bh4[nf]);
#pragma unroll
            for (int mf = 0; mf < 4; mf++)
#pragma unroll
                for (int nf = 0; nf < 4; nf++) MMA_S8(mid[mf][nf], ah[mf], bl4[nf]);
#pragma unroll
            for (int mf = 0; mf < 4; mf++)
#pragma unroll
                for (int nf = 0; nf < 4; nf++) MMA_S8(mid[mf][nf], al[mf], bh4[nf]);
        }

        if (c == 3) {
            // ---- fused epilogue for o-tile ot: dequant + tanh + vre dot ----
            float* part = reinterpret_cast<float*>(smem + OFF_PART);
            const int o0 = ot * 128;
            const int r0 = lid >> 2;
            const int cb = 2 * (lid & 3);
#pragma unroll
            for (int mf = 0; mf < 4; mf++) {
                int R0 = wm * 64 + mf * 16 + r0;
                int R1 = R0 + 8;
                const float* lA = g_l + (size_t)((m0 + R0) / SEQ) * HDIM + o0;
                const float* lB = g_l + (size_t)((m0 + R1) / SEQ) * HDIM + o0;
                float p0 = 0.0f, p1 = 0.0f;
#pragma unroll
                for (int nf = 0; nf < 4; nf++) {
                    int cl = wn * 32 + nf * 8 + cb;
                    float c00 = K1 * (float)hh[mf][nf][0] + K2 * (float)mid[mf][nf][0];
                    float c01 = K1 * (float)hh[mf][nf][1] + K2 * (float)mid[mf][nf][1];
                    float c10 = K1 * (float)hh[mf][nf][2] + K2 * (float)mid[mf][nf][2];
                    float c11 = K1 * (float)hh[mf][nf][3] + K2 * (float)mid[mf][nf][3];
                    p0 += fast_tanh(c00 + lA[cl])     * svre[o0 + cl];
                    p0 += fast_tanh(c01 + lA[cl + 1]) * svre[o0 + cl + 1];
                    p1 += fast_tanh(c10 + lB[cl])     * svre[o0 + cl];
                    p1 += fast_tanh(c11 + lB[cl + 1]) * svre[o0 + cl + 1];
#pragma unroll
                    for (int q = 0; q < 4; q++) { hh[mf][nf][q] = 0; mid[mf][nf][q] = 0; }
                }
                p0 += __shfl_xor_sync(0xffffffffu, p0, 1);
                p0 += __shfl_xor_sync(0xffffffffu, p0, 2);
                p1 += __shfl_xor_sync(0xffffffffu, p1, 1);
                p1 += __shfl_xor_sync(0xffffffffu, p1, 2);
                if ((lid & 3) == 0) {
                    part[R0 * 4 + wn] = p0;
                    part[R1 * 4 + wn] = p1;
                }
            }
            __syncthreads();
            if (tid < 128) {
                float s = part[tid * 4 + 0] + part[tid * 4 + 1]
                        + part[tid * 4 + 2] + part[tid * 4 + 3];
                g_spart[ot][m0 + tid] = s;
            }
        }
        __syncthreads();
    }
}

// =============================================================================
// K3: per-batch softmax over S, context, 2-class head (DRAM roofline, ~140us)
// =============================================================================
__device__ __forceinline__ float block_reduce_max(float v, float* red, int tid) {
    red[tid] = v; __syncthreads();
#pragma unroll
    for (int off = 128; off > 0; off >>= 1) {
        if (tid < off) red[tid] = fmaxf(red[tid], red[tid + off]);
        __syncthreads();
    }
    float r = red[0]; __syncthreads(); return r;
}
__device__ __forceinline__ float block_reduce_sum(float v, float* red, int tid) {
    red[tid] = v; __syncthreads();
#pragma unroll
    for (int off = 128; off > 0; off >>= 1) {
        if (tid < off) red[tid] = red[tid] + red[tid + off];
        __syncthreads();
    }
    float r = red[0]; __syncthreads(); return r;
}

__global__ void __launch_bounds__(256)
finish_kernel(const float* __restrict__ all_mem,
              const float* __restrict__ wre,
              float* __restrict__ out)
{
    const int b = blockIdx.x, tid = threadIdx.x;
    __shared__ float attn[SEQ];
    __shared__ float red[256];

    float sc = -INFINITY;
    if (tid < SEQ) {
        float s = 0.0f;
#pragma unroll
        for (int p = 0; p < NPLANES; p++) s += g_spart[p][(size_t)b * SEQ + tid];
        sc = s;
    }
    float mx = block_reduce_max(sc, red, tid);
    float e = (tid < SEQ) ? expf(sc - mx) : 0.0f;
    float denom = block_reduce_sum(e, red, tid);
    if (tid < SEQ) attn[tid] = e / denom;
    __syncthreads();

    const float* am = all_mem + (size_t)b * SEQ * HDIM;
    float c0 = 0.0f, c1 = 0.0f;
#pragma unroll 4
    for (int s = 0; s < SEQ; s++) {
        float w = attn[s];
        c0 = fmaf(w, am[(size_t)s * HDIM + tid],       c0);
        c1 = fmaf(w, am[(size_t)s * HDIM + tid + 256], c1);
    }
    float p0 = c0 * wre[tid]        + c1 * wre[tid + 256];
    float p1 = c0 * wre[HDIM + tid] + c1 * wre[HDIM + tid + 256];
    float L0 = block_reduce_sum(p0, red, tid);
    float L1 = block_reduce_sum(p1, red, tid);
    if (tid == 0) {
        float m  = fmaxf(L0, L1);
        float e0 = expf(L0 - m), e1 = expf(L1 - m);
        float inv = 1.0f / (e0 + e1);
        out[(size_t)b * 2 + 0] = e0 * inv;
        out[(size_t)b * 2 + 1] = e1 * inv;
    }
}

// =============================================================================
// launch
// =============================================================================
extern "C" void kernel_launch(void* const* d_in, const int* in_sizes, int n_in,
                              void* d_out, int out_size)
{
    const float* all_memory  = (const float*)d_in[0];
    const float* last_memory = (const float*)d_in[1];
    const float* Ur_w        = (const float*)d_in[2];
    const float* Wr_w        = (const float*)d_in[3];
    const float* Vre_w       = (const float*)d_in[4];
    const float* Wre_w       = (const float*)d_in[5];
    float* out = (float*)d_out;

    cudaFuncSetAttribute(score_kernel,
                         cudaFuncAttributeMaxDynamicSharedMemorySize, SMEM_TOTAL);

    bquant_kernel<<<256, 256>>>(Ur_w);
    gemm_l_kernel<<<dim3(BATCH / 64, HDIM / 128), 256>>>(last_memory, Wr_w);
    score_kernel<<<MTOT / 128, 256, SMEM_TOTAL>>>(all_memory, Vre_w);
    finish_kernel<<<BATCH, 256>>>(all_memory, Wre_w, out);
}

// round 5
// speedup vs baseline: 2.2095x; 2.2095x over previous
#include <cuda_runtime.h>
#include <cuda_bf16.h>
#include <math.h>
#include <cstdint>

#define BATCH 2048
#define SEQ   200
#define HDIM  512
#define MTOT  (BATCH * SEQ)   // 409600
#define NPLANES 4             // 4 o-tiles of 128 cols

// ---------------- static device scratch (no allocation) ----------------
__device__ float g_l[BATCH * HDIM];                 // Wr(last_memory)  [B,512]
__device__ float g_spart[NPLANES][MTOT];            // partial scores
__device__ __nv_bfloat16 g_Whi[HDIM * HDIM];        // Ur_w split hi
__device__ __nv_bfloat16 g_Wlo[HDIM * HDIM];        // Ur_w split lo

// ======================= helpers =======================
__device__ __forceinline__ uint32_t smem_u32(const void* p) {
    uint32_t a;
    asm("{ .reg .u64 t; cvta.to.shared.u64 t, %1; cvt.u32.u64 %0, t; }"
        : "=r"(a) : "l"(p));
    return a;
}
#define SWZ(off) ((off) ^ (((off) >> 3) & 0x70))

#define LDSM_X4(r, a) \
    asm volatile("ldmatrix.sync.aligned.m8n8.x4.shared.b16 {%0,%1,%2,%3}, [%4];" \
        : "=r"((r)[0]), "=r"((r)[1]), "=r"((r)[2]), "=r"((r)[3]) : "r"(a))
#define LDSM_X2(r, a) \
    asm volatile("ldmatrix.sync.aligned.m8n8.x2.shared.b16 {%0,%1}, [%2];" \
        : "=r"((r)[0]), "=r"((r)[1]) : "r"(a))
#define MMA_BF16(d, a, b) \
    asm volatile("mma.sync.aligned.m16n8k16.row.col.f32.bf16.bf16.f32 " \
        "{%0,%1,%2,%3},{%4,%5,%6,%7},{%8,%9},{%0,%1,%2,%3};" \
        : "+f"((d)[0]), "+f"((d)[1]), "+f"((d)[2]), "+f"((d)[3]) \
        : "r"((a)[0]), "r"((a)[1]), "r"((a)[2]), "r"((a)[3]), \
          "r"((b)[0]), "r"((b)[1]))
#define CPASYNC16(dst, src) \
    asm volatile("cp.async.cg.shared.global [%0], [%1], 16;" \
        :: "r"(dst), "l"(src) : "memory")
#define CPASYNC_COMMIT() asm volatile("cp.async.commit_group;" ::: "memory")
#define CPASYNC_WAIT0()  asm volatile("cp.async.wait_group 0;" ::: "memory")
#define STS128(addr, a, b, c, d) \
    asm volatile("st.shared.v4.b32 [%0], {%1, %2, %3, %4};" \
        :: "r"(addr), "r"(a), "r"(b), "r"(c), "r"(d) : "memory")

__device__ __forceinline__ float fast_tanh(float x) {
    float e = __expf(2.0f * x);
    return 1.0f - __fdividef(2.0f, e + 1.0f);
}

// =============================================================================
// W split kernel: Ur_w fp32 -> (hi, lo) bf16
// =============================================================================
__global__ void __launch_bounds__(256)
wsplit_kernel(const float* __restrict__ W)
{
    int i = blockIdx.x * 256 + threadIdx.x;          // float4 units
    float4 v = reinterpret_cast<const float4*>(W)[i];
    __nv_bfloat162 h0 = __float22bfloat162_rn(make_float2(v.x, v.y));
    __nv_bfloat162 h1 = __float22bfloat162_rn(make_float2(v.z, v.w));
    __nv_bfloat162 l0 = __float22bfloat162_rn(make_float2(
        v.x - __bfloat162float(h0.x), v.y - __bfloat162float(h0.y)));
    __nv_bfloat162 l1 = __float22bfloat162_rn(make_float2(
        v.z - __bfloat162float(h1.x), v.w - __bfloat162float(h1.y)));
    reinterpret_cast<__nv_bfloat162*>(g_Whi)[2 * i + 0] = h0;
    reinterpret_cast<__nv_bfloat162*>(g_Whi)[2 * i + 1] = h1;
    reinterpret_cast<__nv_bfloat162*>(g_Wlo)[2 * i + 0] = l0;
    reinterpret_cast<__nv_bfloat162*>(g_Wlo)[2 * i + 1] = l1;
}

// =============================================================================
// K1: l = last_memory @ Wr^T  (SIMT fp32, small; ~52us)
// =============================================================================
__global__ void __launch_bounds__(256)
gemm_l_kernel(const float* __restrict__ A, const float* __restrict__ W)
{
    const int tid = threadIdx.x;
    const int tx  = tid & 15;
    const int ty  = tid >> 4;
    const int m0  = blockIdx.x * 64;
    const int o0  = blockIdx.y * 128;

    __shared__ float As[64][33];
    __shared__ float Ws[128][33];

    float acc[4][8];
#pragma unroll
    for (int i = 0; i < 4; i++)
#pragma unroll
        for (int j = 0; j < 8; j++) acc[i][j] = 0.0f;

    for (int k0 = 0; k0 < HDIM; k0 += 32) {
#pragma unroll
        for (int t = 0; t < 2; t++) {
            int f = t * 256 + tid, r = f >> 3, c4 = (f & 7) << 2;
            float4 v = *reinterpret_cast<const float4*>(&A[(size_t)(m0 + r) * HDIM + k0 + c4]);
            As[r][c4] = v.x; As[r][c4 + 1] = v.y; As[r][c4 + 2] = v.z; As[r][c4 + 3] = v.w;
        }
#pragma unroll
        for (int t = 0; t < 4; t++) {
            int f = t * 256 + tid, r = f >> 3, c4 = (f & 7) << 2;
            float4 v = *reinterpret_cast<const float4*>(&W[(size_t)(o0 + r) * HDIM + k0 + c4]);
            Ws[r][c4] = v.x; Ws[r][c4 + 1] = v.y; Ws[r][c4 + 2] = v.z; Ws[r][c4 + 3] = v.w;
        }
        __syncthreads();
#pragma unroll
        for (int kk = 0; kk < 32; kk++) {
            float a[4], w[8];
#pragma unroll
            for (int i = 0; i < 4; i++) a[i] = As[ty * 4 + i][kk];
#pragma unroll
            for (int j = 0; j < 8; j++) w[j] = Ws[tx + 16 * j][kk];
#pragma unroll
            for (int i = 0; i < 4; i++)
#pragma unroll
                for (int j = 0; j < 8; j++) acc[i][j] += a[i] * w[j];
        }
        __syncthreads();
    }
#pragma unroll
    for (int i = 0; i < 4; i++) {
        int m = m0 + ty * 4 + i;
#pragma unroll
        for (int j = 0; j < 8; j++)
            g_l[(size_t)m * HDIM + o0 + tx + 16 * j] = acc[i][j];
    }
}

// =============================================================================
// K2: bf16-split GEMM (3 HMMA passes) + fused tanh/vre epilogue.
// CTA 128(m) x 128(n), single 64KB K=64 stage, occupancy 2 CTAs/SM.
// blockIdx.x = o-plane (fast dim -> adjacent CTAs share A tile in L2),
// blockIdx.y = m tile.
// =============================================================================
#define OFF_VRE  0
#define OFF_STG  1024
#define OFF_AHI  0
#define OFF_ALO  16384
#define OFF_BHI  32768
#define OFF_BLO  49152
#define STAGE_SZ 65536
#define SMEM_TOTAL (OFF_STG + STAGE_SZ)   // 66560 -> 2 CTAs/SM

__global__ void __launch_bounds__(256, 2)
score_kernel(const float* __restrict__ A,       // all_memory [M,512]
             const float* __restrict__ vre)     // [512]
{
    extern __shared__ char smem[];
    const uint32_t sb  = smem_u32(smem);
    const uint32_t st  = sb + OFF_STG;
    const int tid = threadIdx.x;
    const int wid = tid >> 5;
    const int lid = tid & 31;
    const int wm  = wid >> 2;     // 0..1
    const int wn  = wid & 3;      // 0..3
    const int o0  = blockIdx.x * 128;
    const int m0  = blockIdx.y * 128;

    float* svre = reinterpret_cast<float*>(smem + OFF_VRE);
    if (tid < 128) svre[tid] = vre[o0 + tid];

    // producer roles
    const int ar = tid >> 1;                 // A row 0..127
    const int ah = (tid & 1);                // A k half (32 floats)
    const float* Abase = A + (size_t)(m0 + ar) * HDIM + ah * 32;
    const int brow = tid >> 1;
    const int bh   = (tid & 1);
    const __nv_bfloat16* BHbase = g_Whi + (size_t)(o0 + brow) * HDIM + bh * 32;
    const __nv_bfloat16* BLbase = g_Wlo + (size_t)(o0 + brow) * HDIM + bh * 32;
    const uint32_t aoff = (uint32_t)(ar * 128 + ah * 64);
    const uint32_t boff = (uint32_t)(brow * 128 + bh * 64);

    float acc[4][4][4];
#pragma unroll
    for (int i = 0; i < 4; i++)
#pragma unroll
        for (int j = 0; j < 4; j++)
#pragma unroll
            for (int q = 0; q < 4; q++) acc[i][j][q] = 0.0f;

#pragma unroll 1
    for (int c = 0; c < 8; ++c) {
        const int k0 = c * 64;

        // B: cp.async hi/lo (L2-resident weights)
#pragma unroll
        for (int q = 0; q < 4; q++) {
            uint32_t o = SWZ(boff + q * 16);
            CPASYNC16(st + OFF_BHI + o, BHbase + k0 + q * 8);
            CPASYNC16(st + OFF_BLO + o, BLbase + k0 + q * 8);
        }
        CPASYNC_COMMIT();

        // A: load fp32, split to bf16 hi/lo, store swizzled
#pragma unroll
        for (int g = 0; g < 4; g++) {
            float4 u = *reinterpret_cast<const float4*>(Abase + k0 + g * 8);
            float4 v = *reinterpret_cast<const float4*>(Abase + k0 + g * 8 + 4);
            __nv_bfloat162 h0 = __float22bfloat162_rn(make_float2(u.x, u.y));
            __nv_bfloat162 h1 = __float22bfloat162_rn(make_float2(u.z, u.w));
            __nv_bfloat162 h2 = __float22bfloat162_rn(make_float2(v.x, v.y));
            __nv_bfloat162 h3 = __float22bfloat162_rn(make_float2(v.z, v.w));
            __nv_bfloat162 l0 = __float22bfloat162_rn(make_float2(
                u.x - __bfloat162float(h0.x), u.y - __bfloat162float(h0.y)));
            __nv_bfloat162 l1 = __float22bfloat162_rn(make_float2(
                u.z - __bfloat162float(h1.x), u.w - __bfloat162float(h1.y)));
            __nv_bfloat162 l2 = __float22bfloat162_rn(make_float2(
                v.x - __bfloat162float(h2.x), v.y - __bfloat162float(h2.y)));
            __nv_bfloat162 l3 = __float22bfloat162_rn(make_float2(
                v.z - __bfloat162float(h3.x), v.w - __bfloat162float(h3.y)));
            uint32_t o = SWZ(aoff + g * 16);
            STS128(st + OFF_AHI + o,
                   reinterpret_cast<uint32_t&>(h0), reinterpret_cast<uint32_t&>(h1),
                   reinterpret_cast<uint32_t&>(h2), reinterpret_cast<uint32_t&>(h3));
            STS128(st + OFF_ALO + o,
                   reinterpret_cast<uint32_t&>(l0), reinterpret_cast<uint32_t&>(l1),
                   reinterpret_cast<uint32_t&>(l2), reinterpret_cast<uint32_t&>(l3));
        }
        CPASYNC_WAIT0();
        __syncthreads();

        // ---- MMAs (3 split passes) ----
#pragma unroll
        for (int ks = 0; ks < 4; ks++) {
            uint32_t bhi[4][2], blo[4][2];
#pragma unroll
            for (int nf = 0; nf < 4; nf++) {
                uint32_t row = wn * 32 + nf * 8 + (lid & 7);
                uint32_t kb  = ks * 32 + ((lid >> 3) & 1) * 16;
                uint32_t o   = SWZ(row * 128 + kb);
                LDSM_X2(bhi[nf], st + OFF_BHI + o);
                LDSM_X2(blo[nf], st + OFF_BLO + o);
            }
#pragma unroll
            for (int mf = 0; mf < 4; mf++) {
                uint32_t row = wm * 64 + mf * 16 + (lid & 15);
                uint32_t kb  = ks * 32 + (lid >> 4) * 16;
                uint32_t o   = SWZ(row * 128 + kb);
                uint32_t ahi[4], alo[4];
                LDSM_X4(ahi, st + OFF_AHI + o);
                LDSM_X4(alo, st + OFF_ALO + o);
#pragma unroll
                for (int nf = 0; nf < 4; nf++) {
                    MMA_BF16(acc[mf][nf], ahi, bhi[nf]);
                    MMA_BF16(acc[mf][nf], alo, bhi[nf]);
                    MMA_BF16(acc[mf][nf], ahi, blo[nf]);
                }
            }
        }
        __syncthreads();
    }

    // ---- fused epilogue: tanh + vre dot, per-row reduce ----
    float* part = reinterpret_cast<float*>(smem + OFF_STG);   // aliases stage
    const int r0 = lid >> 2;
    const int cb = 2 * (lid & 3);
#pragma unroll
    for (int mf = 0; mf < 4; mf++) {
        int R0 = wm * 64 + mf * 16 + r0;
        int R1 = R0 + 8;
        const float* lA = g_l + (size_t)((m0 + R0) / SEQ) * HDIM + o0;
        const float* lB = g_l + (size_t)((m0 + R1) / SEQ) * HDIM + o0;
        float p0 = 0.0f, p1 = 0.0f;
#pragma unroll
        for (int nf = 0; nf < 4; nf++) {
            int cl = wn * 32 + nf * 8 + cb;
            p0 += fast_tanh(acc[mf][nf][0] + lA[cl])     * svre[cl];
            p0 += fast_tanh(acc[mf][nf][1] + lA[cl + 1]) * svre[cl + 1];
            p1 += fast_tanh(acc[mf][nf][2] + lB[cl])     * svre[cl];
            p1 += fast_tanh(acc[mf][nf][3] + lB[cl + 1]) * svre[cl + 1];
        }
        p0 += __shfl_xor_sync(0xffffffffu, p0, 1);
        p0 += __shfl_xor_sync(0xffffffffu, p0, 2);
        p1 += __shfl_xor_sync(0xffffffffu, p1, 1);
        p1 += __shfl_xor_sync(0xffffffffu, p1, 2);
        if ((lid & 3) == 0) {
            part[R0 * 4 + wn] = p0;
            part[R1 * 4 + wn] = p1;
        }
    }
    __syncthreads();
    if (tid < 128) {
        float s = part[tid * 4 + 0] + part[tid * 4 + 1]
                + part[tid * 4 + 2] + part[tid * 4 + 3];
        g_spart[blockIdx.x][m0 + tid] = s;
    }
}

// =============================================================================
// K3: per-batch softmax over S, context, 2-class head (DRAM roofline ~137us)
// =============================================================================
__device__ __forceinline__ float block_reduce_max(float v, float* red, int tid) {
    red[tid] = v; __syncthreads();
#pragma unroll
    for (int off = 128; off > 0; off >>= 1) {
        if (tid < off) red[tid] = fmaxf(red[tid], red[tid + off]);
        __syncthreads();
    }
    float r = red[0]; __syncthreads(); return r;
}
__device__ __forceinline__ float block_reduce_sum(float v, float* red, int tid) {
    red[tid] = v; __syncthreads();
#pragma unroll
    for (int off = 128; off > 0; off >>= 1) {
        if (tid < off) red[tid] = red[tid] + red[tid + off];
        __syncthreads();
    }
    float r = red[0]; __syncthreads(); return r;
}

__global__ void __launch_bounds__(256)
finish_kernel(const float* __restrict__ all_mem,
              const float* __restrict__ wre,
              float* __restrict__ out)
{
    const int b = blockIdx.x, tid = threadIdx.x;
    __shared__ float attn[SEQ];
    __shared__ float red[256];

    float sc = -INFINITY;
    if (tid < SEQ) {
        float s = 0.0f;
#pragma unroll
        for (int p = 0; p < NPLANES; p++) s += g_spart[p][(size_t)b * SEQ + tid];
        sc = s;
    }
    float mx = block_reduce_max(sc, red, tid);
    float e = (tid < SEQ) ? expf(sc - mx) : 0.0f;
    float denom = block_reduce_sum(e, red, tid);
    if (tid < SEQ) attn[tid] = e / denom;
    __syncthreads();

    const float* am = all_mem + (size_t)b * SEQ * HDIM;
    float c0 = 0.0f, c1 = 0.0f;
#pragma unroll 4
    for (int s = 0; s < SEQ; s++) {
        float w = attn[s];
        c0 = fmaf(w, am[(size_t)s * HDIM + tid],       c0);
        c1 = fmaf(w, am[(size_t)s * HDIM + tid + 256], c1);
    }
    float p0 = c0 * wre[tid]        + c1 * wre[tid + 256];
    float p1 = c0 * wre[HDIM + tid] + c1 * wre[HDIM + tid + 256];
    float L0 = block_reduce_sum(p0, red, tid);
    float L1 = block_reduce_sum(p1, red, tid);
    if (tid == 0) {
        float m  = fmaxf(L0, L1);
        float e0 = expf(L0 - m), e1 = expf(L1 - m);
        float inv = 1.0f / (e0 + e1);
        out[(size_t)b * 2 + 0] = e0 * inv;
        out[(size_t)b * 2 + 1] = e1 * inv;
    }
}

// =============================================================================
// launch
// =============================================================================
extern "C" void kernel_launch(void* const* d_in, const int* in_sizes, int n_in,
                              void* d_out, int out_size)
{
    const float* all_memory  = (const float*)d_in[0];
    const float* last_memory = (const float*)d_in[1];
    const float* Ur_w        = (const float*)d_in[2];
    const float* Wr_w        = (const float*)d_in[3];
    const float* Vre_w       = (const float*)d_in[4];
    const float* Wre_w       = (const float*)d_in[5];
    float* out = (float*)d_out;

    cudaFuncSetAttribute(score_kernel,
                         cudaFuncAttributeMaxDynamicSharedMemorySize, SMEM_TOTAL);

    wsplit_kernel<<<256, 256>>>(Ur_w);
    gemm_l_kernel<<<dim3(BATCH / 64, HDIM / 128), 256>>>(last_memory, Wr_w);
    score_kernel<<<dim3(NPLANES, MTOT / 128), 256, SMEM_TOTAL>>>(all_memory, Vre_w);
    finish_kernel<<<BATCH, 256>>>(all_memory, Wre_w, out);
}

// round 6
// speedup vs baseline: 3.5791x; 1.6198x over previous
#include <cuda_runtime.h>
#include <cuda_fp16.h>
#include <math.h>
#include <cstdint>

#define BATCH 2048
#define SEQ   200
#define HDIM  512
#define MTOT  (BATCH * SEQ)   // 409600
#define NPLANES 4             // 4 o-tiles of 128 cols

// ---------------- static device scratch (no allocation) ----------------
__device__ float g_l[BATCH * HDIM];          // Wr(last_memory)  [B,512]
__device__ float g_spart[NPLANES][MTOT];     // partial scores
__device__ __half g_Wh[HDIM * HDIM];         // Ur_w fp16

// ======================= helpers =======================
__device__ __forceinline__ uint32_t smem_u32(const void* p) {
    uint32_t a;
    asm("{ .reg .u64 t; cvta.to.shared.u64 t, %1; cvt.u32.u64 %0, t; }"
        : "=r"(a) : "l"(p));
    return a;
}
#define SWZ(off) ((off) ^ (((off) >> 3) & 0x70))

#define LDSM_X4(r, a) \
    asm volatile("ldmatrix.sync.aligned.m8n8.x4.shared.b16 {%0,%1,%2,%3}, [%4];" \
        : "=r"((r)[0]), "=r"((r)[1]), "=r"((r)[2]), "=r"((r)[3]) : "r"(a))
#define LDSM_X2(r, a) \
    asm volatile("ldmatrix.sync.aligned.m8n8.x2.shared.b16 {%0,%1}, [%2];" \
        : "=r"((r)[0]), "=r"((r)[1]) : "r"(a))
#define MMA_F16(d, a, b) \
    asm volatile("mma.sync.aligned.m16n8k16.row.col.f32.f16.f16.f32 " \
        "{%0,%1,%2,%3},{%4,%5,%6,%7},{%8,%9},{%0,%1,%2,%3};" \
        : "+f"((d)[0]), "+f"((d)[1]), "+f"((d)[2]), "+f"((d)[3]) \
        : "r"((a)[0]), "r"((a)[1]), "r"((a)[2]), "r"((a)[3]), \
          "r"((b)[0]), "r"((b)[1]))
#define CPASYNC16(dst, src) \
    asm volatile("cp.async.cg.shared.global [%0], [%1], 16;" \
        :: "r"(dst), "l"(src) : "memory")
#define CPASYNC_COMMIT() asm volatile("cp.async.commit_group;" ::: "memory")
#define CPASYNC_WAIT0()  asm volatile("cp.async.wait_group 0;" ::: "memory")
#define STS128(addr, a, b, c, d) \
    asm volatile("st.shared.v4.b32 [%0], {%1, %2, %3, %4};" \
        :: "r"(addr), "r"(a), "r"(b), "r"(c), "r"(d) : "memory")

__device__ __forceinline__ float fast_tanh(float x) {
    float e = __expf(2.0f * x);
    return 1.0f - __fdividef(2.0f, e + 1.0f);
}

// =============================================================================
// W convert kernel: Ur_w fp32 -> fp16
// =============================================================================
__global__ void __launch_bounds__(256)
whalf_kernel(const float* __restrict__ W)
{
    int i = blockIdx.x * 256 + threadIdx.x;          // float4 units, 65536
    float4 v = reinterpret_cast<const float4*>(W)[i];
    __half2 h0 = __float22half2_rn(make_float2(v.x, v.y));
    __half2 h1 = __float22half2_rn(make_float2(v.z, v.w));
    reinterpret_cast<__half2*>(g_Wh)[2 * i + 0] = h0;
    reinterpret_cast<__half2*>(g_Wh)[2 * i + 1] = h1;
}

// =============================================================================
// K1: l = last_memory @ Wr^T  (SIMT fp32, small; ~52us)
// =============================================================================
__global__ void __launch_bounds__(256)
gemm_l_kernel(const float* __restrict__ A, const float* __restrict__ W)
{
    const int tid = threadIdx.x;
    const int tx  = tid & 15;
    const int ty  = tid >> 4;
    const int m0  = blockIdx.x * 64;
    const int o0  = blockIdx.y * 128;

    __shared__ float As[64][33];
    __shared__ float Ws[128][33];

    float acc[4][8];
#pragma unroll
    for (int i = 0; i < 4; i++)
#pragma unroll
        for (int j = 0; j < 8; j++) acc[i][j] = 0.0f;

    for (int k0 = 0; k0 < HDIM; k0 += 32) {
#pragma unroll
        for (int t = 0; t < 2; t++) {
            int f = t * 256 + tid, r = f >> 3, c4 = (f & 7) << 2;
            float4 v = *reinterpret_cast<const float4*>(&A[(size_t)(m0 + r) * HDIM + k0 + c4]);
            As[r][c4] = v.x; As[r][c4 + 1] = v.y; As[r][c4 + 2] = v.z; As[r][c4 + 3] = v.w;
        }
#pragma unroll
        for (int t = 0; t < 4; t++) {
            int f = t * 256 + tid, r = f >> 3, c4 = (f & 7) << 2;
            float4 v = *reinterpret_cast<const float4*>(&W[(size_t)(o0 + r) * HDIM + k0 + c4]);
            Ws[r][c4] = v.x; Ws[r][c4 + 1] = v.y; Ws[r][c4 + 2] = v.z; Ws[r][c4 + 3] = v.w;
        }
        __syncthreads();
#pragma unroll
        for (int kk = 0; kk < 32; kk++) {
            float a[4], w[8];
#pragma unroll
            for (int i = 0; i < 4; i++) a[i] = As[ty * 4 + i][kk];
#pragma unroll
            for (int j = 0; j < 8; j++) w[j] = Ws[tx + 16 * j][kk];
#pragma unroll
            for (int i = 0; i < 4; i++)
#pragma unroll
                for (int j = 0; j < 8; j++) acc[i][j] += a[i] * w[j];
        }
        __syncthreads();
    }
#pragma unroll
    for (int i = 0; i < 4; i++) {
        int m = m0 + ty * 4 + i;
#pragma unroll
        for (int j = 0; j < 8; j++)
            g_l[(size_t)m * HDIM + o0 + tx + 16 * j] = acc[i][j];
    }
}

// =============================================================================
// K2: single-pass fp16 HMMA GEMM + fused tanh/vre epilogue.
// CTA 128(m) x 128(n); K=64 stages, double-buffered (2x32KB), occ 2 CTAs/SM.
// blockIdx.x = o-plane (fast dim: L2 A-tile sharing), blockIdx.y = m tile.
// =============================================================================
#define OFF_VRE  0
#define OFF_STG  1024
#define OFF_A    0
#define OFF_B    16384
#define STAGE_SZ 32768
#define SMEM_TOTAL (OFF_STG + 2 * STAGE_SZ)   // 66560

__global__ void __launch_bounds__(256, 2)
score_kernel(const float* __restrict__ A,       // all_memory [M,512]
             const float* __restrict__ vre)     // [512]
{
    extern __shared__ char smem[];
    const uint32_t sb  = smem_u32(smem);
    const int tid = threadIdx.x;
    const int wid = tid >> 5;
    const int lid = tid & 31;
    const int wm  = wid >> 2;     // 0..1
    const int wn  = wid & 3;      // 0..3
    const int o0  = blockIdx.x * 128;
    const int m0  = blockIdx.y * 128;

    float* svre = reinterpret_cast<float*>(smem + OFF_VRE);
    if (tid < 128) svre[tid] = vre[o0 + tid];

    // producer roles: 32 floats of A / 32 halfs of B per thread per chunk
    const int ar = tid >> 1;
    const int ah = (tid & 1);
    const float* Abase = A + (size_t)(m0 + ar) * HDIM + ah * 32;
    const int brow = tid >> 1;
    const int bh   = (tid & 1);
    const __half* Bbase = g_Wh + (size_t)(o0 + brow) * HDIM + bh * 32;
    const uint32_t aoff = (uint32_t)(ar * 128 + ah * 64);
    const uint32_t boff = (uint32_t)(brow * 128 + bh * 64);

    float acc[4][4][4];
#pragma unroll
    for (int i = 0; i < 4; i++)
#pragma unroll
        for (int j = 0; j < 4; j++)
#pragma unroll
            for (int q = 0; q < 4; q++) acc[i][j][q] = 0.0f;

    float4 va[8];

    // ---- prologue: stage chunk 0 ----
    {
        const uint32_t st = sb + OFF_STG;
#pragma unroll
        for (int q = 0; q < 4; q++)
            CPASYNC16(st + OFF_B + SWZ(boff + q * 16), Bbase + q * 8);
        CPASYNC_COMMIT();
#pragma unroll
        for (int q = 0; q < 8; q++)
            va[q] = *reinterpret_cast<const float4*>(Abase + q * 4);
#pragma unroll
        for (int g = 0; g < 4; g++) {
            float4 u = va[2 * g], v = va[2 * g + 1];
            __half2 h0 = __float22half2_rn(make_float2(u.x, u.y));
            __half2 h1 = __float22half2_rn(make_float2(u.z, u.w));
            __half2 h2 = __float22half2_rn(make_float2(v.x, v.y));
            __half2 h3 = __float22half2_rn(make_float2(v.z, v.w));
            STS128(st + OFF_A + SWZ(aoff + g * 16),
                   reinterpret_cast<uint32_t&>(h0), reinterpret_cast<uint32_t&>(h1),
                   reinterpret_cast<uint32_t&>(h2), reinterpret_cast<uint32_t&>(h3));
        }
        CPASYNC_WAIT0();
        __syncthreads();
    }

#pragma unroll 1
    for (int c = 0; c < 8; ++c) {
        const uint32_t st  = sb + OFF_STG + (c & 1) * STAGE_SZ;
        const uint32_t stn = sb + OFF_STG + ((c + 1) & 1) * STAGE_SZ;

        // prefetch next chunk (B cp.async + A gmem loads) to overlap with MMA
        if (c < 7) {
            const int k1 = (c + 1) * 64;
#pragma unroll
            for (int q = 0; q < 4; q++)
                CPASYNC16(stn + OFF_B + SWZ(boff + q * 16), Bbase + k1 + q * 8);
            CPASYNC_COMMIT();
#pragma unroll
            for (int q = 0; q < 8; q++)
                va[q] = *reinterpret_cast<const float4*>(Abase + k1 + q * 4);
        }

        // ---- MMAs on stage st ----
#pragma unroll
        for (int ks = 0; ks < 4; ks++) {
            uint32_t bf[4][2];
#pragma unroll
            for (int nf = 0; nf < 4; nf++) {
                uint32_t row = wn * 32 + nf * 8 + (lid & 7);
                uint32_t kb  = ks * 32 + ((lid >> 3) & 1) * 16;
                LDSM_X2(bf[nf], st + OFF_B + SWZ(row * 128 + kb));
            }
#pragma unroll
            for (int mf = 0; mf < 4; mf++) {
                uint32_t row = wm * 64 + mf * 16 + (lid & 15);
                uint32_t kb  = ks * 32 + (lid >> 4) * 16;
                uint32_t af[4];
                LDSM_X4(af, st + OFF_A + SWZ(row * 128 + kb));
#pragma unroll
                for (int nf = 0; nf < 4; nf++)
                    MMA_F16(acc[mf][nf], af, bf[nf]);
            }
        }

        // convert + store next A chunk
        if (c < 7) {
#pragma unroll
            for (int g = 0; g < 4; g++) {
                float4 u = va[2 * g], v = va[2 * g + 1];
                __half2 h0 = __float22half2_rn(make_float2(u.x, u.y));
                __half2 h1 = __float22half2_rn(make_float2(u.z, u.w));
                __half2 h2 = __float22half2_rn(make_float2(v.x, v.y));
                __half2 h3 = __float22half2_rn(make_float2(v.z, v.w));
                STS128(stn + OFF_A + SWZ(aoff + g * 16),
                       reinterpret_cast<uint32_t&>(h0), reinterpret_cast<uint32_t&>(h1),
                       reinterpret_cast<uint32_t&>(h2), reinterpret_cast<uint32_t&>(h3));
            }
            CPASYNC_WAIT0();
        }
        __syncthreads();
    }

    // ---- fused epilogue: tanh + vre dot, per-row reduce ----
    float* part = reinterpret_cast<float*>(smem + OFF_STG);   // aliases stage
    const int r0 = lid >> 2;
    const int cb = 2 * (lid & 3);
#pragma unroll
    for (int mf = 0; mf < 4; mf++) {
        int R0 = wm * 64 + mf * 16 + r0;
        int R1 = R0 + 8;
        const float* lA = g_l + (size_t)((m0 + R0) / SEQ) * HDIM + o0;
        const float* lB = g_l + (size_t)((m0 + R1) / SEQ) * HDIM + o0;
        float p0 = 0.0f, p1 = 0.0f;
#pragma unroll
        for (int nf = 0; nf < 4; nf++) {
            int cl = wn * 32 + nf * 8 + cb;
            p0 += fast_tanh(acc[mf][nf][0] + lA[cl])     * svre[cl];
            p0 += fast_tanh(acc[mf][nf][1] + lA[cl + 1]) * svre[cl + 1];
            p1 += fast_tanh(acc[mf][nf][2] + lB[cl])     * svre[cl];
            p1 += fast_tanh(acc[mf][nf][3] + lB[cl + 1]) * svre[cl + 1];
        }
        p0 += __shfl_xor_sync(0xffffffffu, p0, 1);
        p0 += __shfl_xor_sync(0xffffffffu, p0, 2);
        p1 += __shfl_xor_sync(0xffffffffu, p1, 1);
        p1 += __shfl_xor_sync(0xffffffffu, p1, 2);
        if ((lid & 3) == 0) {
            part[R0 * 4 + wn] = p0;
            part[R1 * 4 + wn] = p1;
        }
    }
    __syncthreads();
    if (tid < 128) {
        float s = part[tid * 4 + 0] + part[tid * 4 + 1]
                + part[tid * 4 + 2] + part[tid * 4 + 3];
        g_spart[blockIdx.x][m0 + tid] = s;
    }
}

// =============================================================================
// K3: per-batch softmax over S, context, 2-class head (DRAM roofline ~140us)
// =============================================================================
__device__ __forceinline__ float block_reduce_max(float v, float* red, int tid) {
    red[tid] = v; __syncthreads();
#pragma unroll
    for (int off = 128; off > 0; off >>= 1) {
        if (tid < off) red[tid] = fmaxf(red[tid], red[tid + off]);
        __syncthreads();
    }
    float r = red[0]; __syncthreads(); return r;
}
__device__ __forceinline__ float block_reduce_sum(float v, float* red, int tid) {
    red[tid] = v; __syncthreads();
#pragma unroll
    for (int off = 128; off > 0; off >>= 1) {
        if (tid < off) red[tid] = red[tid] + red[tid + off];
        __syncthreads();
    }
    float r = red[0]; __syncthreads(); return r;
}

__global__ void __launch_bounds__(256)
finish_kernel(const float* __restrict__ all_mem,
              const float* __restrict__ wre,
              float* __restrict__ out)
{
    const int b = blockIdx.x, tid = threadIdx.x;
    __shared__ float attn[SEQ];
    __shared__ float red[256];

    float sc = -INFINITY;
    if (tid < SEQ) {
        float s = 0.0f;
#pragma unroll
        for (int p = 0; p < NPLANES; p++) s += g_spart[p][(size_t)b * SEQ + tid];
        sc = s;
    }
    float mx = block_reduce_max(sc, red, tid);
    float e = (tid < SEQ) ? expf(sc - mx) : 0.0f;
    float denom = block_reduce_sum(e, red, tid);
    if (tid < SEQ) attn[tid] = e / denom;
    __syncthreads();

    const float* am = all_mem + (size_t)b * SEQ * HDIM;
    float c0 = 0.0f, c1 = 0.0f;
#pragma unroll 4
    for (int s = 0; s < SEQ; s++) {
        float w = attn[s];
        c0 = fmaf(w, am[(size_t)s * HDIM + tid],       c0);
        c1 = fmaf(w, am[(size_t)s * HDIM + tid + 256], c1);
    }
    float p0 = c0 * wre[tid]        + c1 * wre[tid + 256];
    float p1 = c0 * wre[HDIM + tid] + c1 * wre[HDIM + tid + 256];
    float L0 = block_reduce_sum(p0, red, tid);
    float L1 = block_reduce_sum(p1, red, tid);
    if (tid == 0) {
        float m  = fmaxf(L0, L1);
        float e0 = expf(L0 - m), e1 = expf(L1 - m);
        float inv = 1.0f / (e0 + e1);
        out[(size_t)b * 2 + 0] = e0 * inv;
        out[(size_t)b * 2 + 1] = e1 * inv;
    }
}

// =============================================================================
// launch
// =============================================================================
extern "C" void kernel_launch(void* const* d_in, const int* in_sizes, int n_in,
                              void* d_out, int out_size)
{
    const float* all_memory  = (const float*)d_in[0];
    const float* last_memory = (const float*)d_in[1];
    const float* Ur_w        = (const float*)d_in[2];
    const float* Wr_w        = (const float*)d_in[3];
    const float* Vre_w       = (const float*)d_in[4];
    const float* Wre_w       = (const float*)d_in[5];
    float* out = (float*)d_out;

    cudaFuncSetAttribute(score_kernel,
                         cudaFuncAttributeMaxDynamicSharedMemorySize, SMEM_TOTAL);

    whalf_kernel<<<256, 256>>>(Ur_w);
    gemm_l_kernel<<<dim3(BATCH / 64, HDIM / 128), 256>>>(last_memory, Wr_w);
    score_kernel<<<dim3(NPLANES, MTOT / 128), 256, SMEM_TOTAL>>>(all_memory, Vre_w);
    finish_kernel<<<BATCH, 256>>>(all_memory, Wre_w, out);
}

// round 7
// speedup vs baseline: 4.0962x; 1.1445x over previous
#include <cuda_runtime.h>
#include <cuda_fp16.h>
#include <math.h>
#include <cstdint>

#define BATCH 2048
#define SEQ   200
#define HDIM  512
#define MTOT  (BATCH * SEQ)   // 409600
#define NPLANES 4             // 4 o-tiles of 128 cols

// ---------------- static device scratch (no allocation) ----------------
__device__ float  g_l[BATCH * HDIM];          // Wr(last_memory)  [B,512]
__device__ float  g_spart[NPLANES][MTOT];     // partial scores
__device__ __half g_Wh[HDIM * HDIM];          // Ur_w fp16
__device__ __half g_Ah[(size_t)MTOT * HDIM];  // all_memory fp16 (419 MB)

// ======================= helpers =======================
__device__ __forceinline__ uint32_t smem_u32(const void* p) {
    uint32_t a;
    asm("{ .reg .u64 t; cvta.to.shared.u64 t, %1; cvt.u32.u64 %0, t; }"
        : "=r"(a) : "l"(p));
    return a;
}
#define SWZ(off) ((off) ^ (((off) >> 3) & 0x70))

#define LDSM_X4(r, a) \
    asm volatile("ldmatrix.sync.aligned.m8n8.x4.shared.b16 {%0,%1,%2,%3}, [%4];" \
        : "=r"((r)[0]), "=r"((r)[1]), "=r"((r)[2]), "=r"((r)[3]) : "r"(a))
#define LDSM_X2(r, a) \
    asm volatile("ldmatrix.sync.aligned.m8n8.x2.shared.b16 {%0,%1}, [%2];" \
        : "=r"((r)[0]), "=r"((r)[1]) : "r"(a))
#define MMA_F16(d, a, b) \
    asm volatile("mma.sync.aligned.m16n8k16.row.col.f32.f16.f16.f32 " \
        "{%0,%1,%2,%3},{%4,%5,%6,%7},{%8,%9},{%0,%1,%2,%3};" \
        : "+f"((d)[0]), "+f"((d)[1]), "+f"((d)[2]), "+f"((d)[3]) \
        : "r"((a)[0]), "r"((a)[1]), "r"((a)[2]), "r"((a)[3]), \
          "r"((b)[0]), "r"((b)[1]))
#define CPASYNC16(dst, src) \
    asm volatile("cp.async.cg.shared.global [%0], [%1], 16;" \
        :: "r"(dst), "l"(src) : "memory")
#define CPASYNC_COMMIT() asm volatile("cp.async.commit_group;" ::: "memory")
#define CPASYNC_WAITG(n) asm volatile("cp.async.wait_group %0;" :: "n"(n) : "memory")

__device__ __forceinline__ float fast_tanh(float x) {
    float e = __expf(2.0f * x);
    return 1.0f - __fdividef(2.0f, e + 1.0f);
}

// =============================================================================
// prep kernel: three independent jobs dispatched by blockIdx.x
//   [0, CONVB)            : all_memory fp32 -> g_Ah fp16  (DRAM-bound, ~210us)
//   [CONVB, CONVB+256)    : Ur_w fp32 -> g_Wh fp16
//   [CONVB+256, +128)     : l = last_memory @ Wr^T -> g_l  (SIMT fp32)
// =============================================================================
#define CONVB 102400
#define PREP_GRID (CONVB + 256 + 128)

__global__ void __launch_bounds__(256)
prep_kernel(const float* __restrict__ A,       // all_memory
            const float* __restrict__ Ur,      // [512,512]
            const float* __restrict__ lastm,   // [2048,512]
            const float* __restrict__ Wr)      // [512,512]
{
    const int tid = threadIdx.x;
    const int bid = blockIdx.x;

    if (bid < CONVB) {
        // ---- A convert: 8 floats per thread ----
        size_t gid = (size_t)bid * 256 + tid;
        float4 u = reinterpret_cast<const float4*>(A)[2 * gid];
        float4 v = reinterpret_cast<const float4*>(A)[2 * gid + 1];
        __half2 h0 = __float22half2_rn(make_float2(u.x, u.y));
        __half2 h1 = __float22half2_rn(make_float2(u.z, u.w));
        __half2 h2 = __float22half2_rn(make_float2(v.x, v.y));
        __half2 h3 = __float22half2_rn(make_float2(v.z, v.w));
        uint4 o;
        o.x = reinterpret_cast<uint32_t&>(h0); o.y = reinterpret_cast<uint32_t&>(h1);
        o.z = reinterpret_cast<uint32_t&>(h2); o.w = reinterpret_cast<uint32_t&>(h3);
        reinterpret_cast<uint4*>(g_Ah)[gid] = o;
        return;
    }
    if (bid < CONVB + 256) {
        // ---- W convert ----
        int i = (bid - CONVB) * 256 + tid;       // float4 units, 65536
        float4 v = reinterpret_cast<const float4*>(Ur)[i];
        __half2 h0 = __float22half2_rn(make_float2(v.x, v.y));
        __half2 h1 = __float22half2_rn(make_float2(v.z, v.w));
        reinterpret_cast<__half2*>(g_Wh)[2 * i + 0] = h0;
        reinterpret_cast<__half2*>(g_Wh)[2 * i + 1] = h1;
        return;
    }
    // ---- gemm_l ----
    {
        const int idx = bid - (CONVB + 256);     // 0..127
        const int m0  = (idx >> 2) * 64;
        const int o0  = (idx & 3) * 128;
        const int tx  = tid & 15;
        const int ty  = tid >> 4;

        __shared__ float As[64][33];
        __shared__ float Ws[128][33];

        float acc[4][8];
#pragma unroll
        for (int i = 0; i < 4; i++)
#pragma unroll
            for (int j = 0; j < 8; j++) acc[i][j] = 0.0f;

        for (int k0 = 0; k0 < HDIM; k0 += 32) {
#pragma unroll
            for (int t = 0; t < 2; t++) {
                int f = t * 256 + tid, r = f >> 3, c4 = (f & 7) << 2;
                float4 v = *reinterpret_cast<const float4*>(
                    &lastm[(size_t)(m0 + r) * HDIM + k0 + c4]);
                As[r][c4] = v.x; As[r][c4 + 1] = v.y;
                As[r][c4 + 2] = v.z; As[r][c4 + 3] = v.w;
            }
#pragma unroll
            for (int t = 0; t < 4; t++) {
                int f = t * 256 + tid, r = f >> 3, c4 = (f & 7) << 2;
                float4 v = *reinterpret_cast<const float4*>(
                    &Wr[(size_t)(o0 + r) * HDIM + k0 + c4]);
                Ws[r][c4] = v.x; Ws[r][c4 + 1] = v.y;
                Ws[r][c4 + 2] = v.z; Ws[r][c4 + 3] = v.w;
            }
            __syncthreads();
#pragma unroll
            for (int kk = 0; kk < 32; kk++) {
                float a[4], w[8];
#pragma unroll
                for (int i = 0; i < 4; i++) a[i] = As[ty * 4 + i][kk];
#pragma unroll
                for (int j = 0; j < 8; j++) w[j] = Ws[tx + 16 * j][kk];
#pragma unroll
                for (int i = 0; i < 4; i++)
#pragma unroll
                    for (int j = 0; j < 8; j++) acc[i][j] += a[i] * w[j];
            }
            __syncthreads();
        }
#pragma unroll
        for (int i = 0; i < 4; i++) {
            int m = m0 + ty * 4 + i;
#pragma unroll
            for (int j = 0; j < 8; j++)
                g_l[(size_t)m * HDIM + o0 + tx + 16 * j] = acc[i][j];
        }
    }
}

// =============================================================================
// K2: fp16 HMMA GEMM, pure cp.async producer, 3-stage pipeline.
// CTA 128(m) x 128(n); stage = 32KB (A 16K + B 16K); 3 stages; occ 2 CTAs/SM.
// blockIdx.x = o-plane (L2 A-tile sharing), blockIdx.y = m tile.
// =============================================================================
#define OFF_VRE  0
#define OFF_STG  1024
#define OFF_B    16384
#define STAGE_SZ 32768
#define SMEM_TOTAL (OFF_STG + 3 * STAGE_SZ)   // 99328 -> 2 CTAs/SM (198656 <= 228K)

__global__ void __launch_bounds__(256, 2)
score_kernel(const float* __restrict__ vre)     // [512]
{
    extern __shared__ char smem[];
    const uint32_t sb  = smem_u32(smem);
    const int tid = threadIdx.x;
    const int wid = tid >> 5;
    const int lid = tid & 31;
    const int wm  = wid >> 2;     // 0..1
    const int wn  = wid & 3;      // 0..3
    const int o0  = blockIdx.x * 128;
    const int m0  = blockIdx.y * 128;

    float* svre = reinterpret_cast<float*>(smem + OFF_VRE);
    if (tid < 128) svre[tid] = vre[o0 + tid];

    // producer roles: 64B of A + 64B of B per thread per chunk (cp.async only)
    const int ar = tid >> 1;
    const int ah = (tid & 1);
    const __half* Abase = g_Ah + (size_t)(m0 + ar) * HDIM + ah * 32;
    const __half* Bbase = g_Wh + (size_t)(o0 + ar) * HDIM + ah * 32;
    const uint32_t roff = (uint32_t)(ar * 128 + ah * 64);

    float acc[4][4][4];
#pragma unroll
    for (int i = 0; i < 4; i++)
#pragma unroll
        for (int j = 0; j < 4; j++)
#pragma unroll
            for (int q = 0; q < 4; q++) acc[i][j][q] = 0.0f;

    // ---- prologue: fill stages 0,1 (chunks 0,1) ----
#pragma unroll
    for (int p = 0; p < 2; p++) {
        const uint32_t st = sb + OFF_STG + p * STAGE_SZ;
        const int k0 = p * 64;
#pragma unroll
        for (int q = 0; q < 4; q++) {
            uint32_t o = SWZ(roff + q * 16);
            CPASYNC16(st + o,         Abase + k0 + q * 8);
            CPASYNC16(st + OFF_B + o, Bbase + k0 + q * 8);
        }
        CPASYNC_COMMIT();
    }

#pragma unroll 1
    for (int c = 0; c < 8; ++c) {
        if (c < 7) { CPASYNC_WAITG(1); } else { CPASYNC_WAITG(0); }
        __syncthreads();

        // fill stage c+2 (overlaps with this chunk's MMAs)
        if (c + 2 < 8) {
            const uint32_t stn = sb + OFF_STG + ((c + 2) % 3) * STAGE_SZ;
            const int k1 = (c + 2) * 64;
#pragma unroll
            for (int q = 0; q < 4; q++) {
                uint32_t o = SWZ(roff + q * 16);
                CPASYNC16(stn + o,         Abase + k1 + q * 8);
                CPASYNC16(stn + OFF_B + o, Bbase + k1 + q * 8);
            }
            CPASYNC_COMMIT();
        }

        // ---- MMAs on stage c%3 ----
        const uint32_t st = sb + OFF_STG + (c % 3) * STAGE_SZ;
#pragma unroll
        for (int ks = 0; ks < 4; ks++) {
            uint32_t bf[4][2];
#pragma unroll
            for (int nf = 0; nf < 4; nf++) {
                uint32_t row = wn * 32 + nf * 8 + (lid & 7);
                uint32_t kb  = ks * 32 + ((lid >> 3) & 1) * 16;
                LDSM_X2(bf[nf], st + OFF_B + SWZ(row * 128 + kb));
            }
#pragma unroll
            for (int mf = 0; mf < 4; mf++) {
                uint32_t row = wm * 64 + mf * 16 + (lid & 15);
                uint32_t kb  = ks * 32 + (lid >> 4) * 16;
                uint32_t af[4];
                LDSM_X4(af, st + SWZ(row * 128 + kb));
#pragma unroll
                for (int nf = 0; nf < 4; nf++)
                    MMA_F16(acc[mf][nf], af, bf[nf]);
            }
        }
    }

    // ---- fused epilogue: tanh + vre dot, per-row reduce ----
    float* part = reinterpret_cast<float*>(smem + OFF_STG);   // aliases stage 0
    const int r0 = lid >> 2;
    const int cb = 2 * (lid & 3);
#pragma unroll
    for (int mf = 0; mf < 4; mf++) {
        int R0 = wm * 64 + mf * 16 + r0;
        int R1 = R0 + 8;
        const float* lA = g_l + (size_t)((m0 + R0) / SEQ) * HDIM + o0;
        const float* lB = g_l + (size_t)((m0 + R1) / SEQ) * HDIM + o0;
        float p0 = 0.0f, p1 = 0.0f;
#pragma unroll
        for (int nf = 0; nf < 4; nf++) {
            int cl = wn * 32 + nf * 8 + cb;
            p0 += fast_tanh(acc[mf][nf][0] + lA[cl])     * svre[cl];
            p0 += fast_tanh(acc[mf][nf][1] + lA[cl + 1]) * svre[cl + 1];
            p1 += fast_tanh(acc[mf][nf][2] + lB[cl])     * svre[cl];
            p1 += fast_tanh(acc[mf][nf][3] + lB[cl + 1]) * svre[cl + 1];
        }
        p0 += __shfl_xor_sync(0xffffffffu, p0, 1);
        p0 += __shfl_xor_sync(0xffffffffu, p0, 2);
        p1 += __shfl_xor_sync(0xffffffffu, p1, 1);
        p1 += __shfl_xor_sync(0xffffffffu, p1, 2);
        if ((lid & 3) == 0) {
            part[R0 * 4 + wn] = p0;
            part[R1 * 4 + wn] = p1;
        }
    }
    __syncthreads();
    if (tid < 128) {
        float s = part[tid * 4 + 0] + part[tid * 4 + 1]
                + part[tid * 4 + 2] + part[tid * 4 + 3];
        g_spart[blockIdx.x][m0 + tid] = s;
    }
}

// =============================================================================
// K3: per-batch softmax over S, context (from fp16 A), 2-class head
// =============================================================================
__device__ __forceinline__ float block_reduce_max(float v, float* red, int tid) {
    red[tid] = v; __syncthreads();
#pragma unroll
    for (int off = 128; off > 0; off >>= 1) {
        if (tid < off) red[tid] = fmaxf(red[tid], red[tid + off]);
        __syncthreads();
    }
    float r = red[0]; __syncthreads(); return r;
}
__device__ __forceinline__ float block_reduce_sum(float v, float* red, int tid) {
    red[tid] = v; __syncthreads();
#pragma unroll
    for (int off = 128; off > 0; off >>= 1) {
        if (tid < off) red[tid] = red[tid] + red[tid + off];
        __syncthreads();
    }
    float r = red[0]; __syncthreads(); return r;
}

__global__ void __launch_bounds__(256)
finish_kernel(const float* __restrict__ wre,
              float* __restrict__ out)
{
    const int b = blockIdx.x, tid = threadIdx.x;
    __shared__ float attn[SEQ];
    __shared__ float red[256];

    float sc = -INFINITY;
    if (tid < SEQ) {
        float s = 0.0f;
#pragma unroll
        for (int p = 0; p < NPLANES; p++) s += g_spart[p][(size_t)b * SEQ + tid];
        sc = s;
    }
    float mx = block_reduce_max(sc, red, tid);
    float e = (tid < SEQ) ? expf(sc - mx) : 0.0f;
    float denom = block_reduce_sum(e, red, tid);
    if (tid < SEQ) attn[tid] = e / denom;
    __syncthreads();

    // ctx from fp16 A: thread handles columns 2*tid, 2*tid+1
    const __half* am = g_Ah + (size_t)b * SEQ * HDIM;
    float c0 = 0.0f, c1 = 0.0f;
#pragma unroll 4
    for (int s = 0; s < SEQ; s++) {
        float w = attn[s];
        __half2 h = *reinterpret_cast<const __half2*>(am + (size_t)s * HDIM + 2 * tid);
        float2 f = __half22float2(h);
        c0 = fmaf(w, f.x, c0);
        c1 = fmaf(w, f.y, c1);
    }
    float p0 = c0 * wre[2 * tid]        + c1 * wre[2 * tid + 1];
    float p1 = c0 * wre[HDIM + 2 * tid] + c1 * wre[HDIM + 2 * tid + 1];
    float L0 = block_reduce_sum(p0, red, tid);
    float L1 = block_reduce_sum(p1, red, tid);
    if (tid == 0) {
        float m  = fmaxf(L0, L1);
        float e0 = expf(L0 - m), e1 = expf(L1 - m);
        float inv = 1.0f / (e0 + e1);
        out[(size_t)b * 2 + 0] = e0 * inv;
        out[(size_t)b * 2 + 1] = e1 * inv;
    }
}

// =============================================================================
// launch
// =============================================================================
extern "C" void kernel_launch(void* const* d_in, const int* in_sizes, int n_in,
                              void* d_out, int out_size)
{
    const float* all_memory  = (const float*)d_in[0];
    const float* last_memory = (const float*)d_in[1];
    const float* Ur_w        = (const float*)d_in[2];
    const float* Wr_w        = (const float*)d_in[3];
    const float* Vre_w       = (const float*)d_in[4];
    const float* Wre_w       = (const float*)d_in[5];
    float* out = (float*)d_out;

    cudaFuncSetAttribute(score_kernel,
                         cudaFuncAttributeMaxDynamicSharedMemorySize, SMEM_TOTAL);

    prep_kernel<<<PREP_GRID, 256>>>(all_memory, Ur_w, last_memory, Wr_w);
    score_kernel<<<dim3(NPLANES, MTOT / 128), 256, SMEM_TOTAL>>>(Vre_w);
    finish_kernel<<<BATCH, 256>>>(Wre_w, out);
}